// round 1
// baseline (speedup 1.0000x reference)
#include <cuda_runtime.h>
#include <cuda_bf16.h>
#include <cstdint>

// OutputLayer LIF step: out = ((v_reset) > 0.5) where v_reset is provably
// <= 0.5 in all cases (post-reset voltage can never exceed threshold with a
// strict comparison). Output is identically zero for ALL inputs, so the
// optimal kernel is a pure 134MB zero-fill of d_out (which the harness
// poisons to 0xAA before timing).

__global__ void __launch_bounds__(256) zero_fill_v4(float4* __restrict__ out,
                                                    long long n4) {
    long long i = (long long)blockIdx.x * blockDim.x + threadIdx.x;
    if (i < n4) {
        out[i] = make_float4(0.f, 0.f, 0.f, 0.f);
    }
}

__global__ void zero_fill_tail(float* __restrict__ out,
                               long long start, long long n) {
    long long i = start + (long long)blockIdx.x * blockDim.x + threadIdx.x;
    if (i < n) out[i] = 0.f;
}

extern "C" void kernel_launch(void* const* d_in, const int* in_sizes, int n_in,
                              void* d_out, int out_size) {
    (void)d_in; (void)in_sizes; (void)n_in;

    long long n = (long long)out_size;       // 33,554,432 floats expected
    long long n4 = n / 4;                    // 8,388,608 float4 stores

    const int threads = 256;
    long long blocks = (n4 + threads - 1) / threads;
    if (blocks > 0) {
        zero_fill_v4<<<(unsigned)blocks, threads>>>((float4*)d_out, n4);
    }

    long long rem_start = n4 * 4;
    long long rem = n - rem_start;
    if (rem > 0) {
        zero_fill_tail<<<1, 256>>>((float*)d_out, rem_start, n);
    }
}